// round 3
// baseline (speedup 1.0000x reference)
#include <cuda_runtime.h>

// ConvDecoder: 2-layer ConvLSTM decoder, fp32 direct-conv baseline.
// B=8, T=10, C=64 in/out, CH=128 hidden, H=W=64, 3x3 'SAME' convs.

#define BB 8
#define TT 10
#define CX 64
#define CH 128
#define HH 64
#define WW 64
#define HW 4096
#define GG (4*CH)   // 512 gate channels

// ---- persistent scratch (device globals; no allocation allowed) ----
__device__ float g_h0[BB*CH*HW];
__device__ float g_c0[BB*CH*HW];
__device__ float g_h1[BB*CH*HW];
__device__ float g_c1[BB*CH*HW];
__device__ float g_gates[BB*GG*HW];

// ---- copy initial states into mutable buffers ----
__global__ void init_states(const float* __restrict__ h0, const float* __restrict__ c0,
                            const float* __restrict__ h1, const float* __restrict__ c1) {
    int n = BB*CH*HW;
    for (int i = blockIdx.x*blockDim.x + threadIdx.x; i < n; i += gridDim.x*blockDim.x) {
        g_h0[i] = h0[i];
        g_c0[i] = c0[i];
        g_h1[i] = h1[i];
        g_c1[i] = c1[i];
    }
}

// ---- generic fused 3x3 conv: out = conv(in1,w1)+b1 [+ conv(in2,w2)+b2] ----
// Tile: 16 rows x 32 cols of output, 16 output channels per block, 256 threads.
// Each thread computes 2 pixels (rows py and py+8) for all 16 output channels.
__global__ __launch_bounds__(256)
void conv3x3_kernel(const float* __restrict__ in1, int cin1, long in1_bstride,
                    const float* __restrict__ w1, const float* __restrict__ b1,
                    const float* __restrict__ in2, int cin2,
                    const float* __restrict__ w2, const float* __restrict__ b2,
                    float* __restrict__ out, long out_bstride)
{
    __shared__ float s_in[18][34];
    __shared__ float s_w[16][9];

    const int tid   = threadIdx.x;
    const int tileX = blockIdx.x & 1;          // W/32 = 2
    const int tileY = blockIdx.x >> 1;         // H/16 = 4
    const int oBase = blockIdx.y * 16;
    const int b     = blockIdx.z;
    const int px    = tid & 31;
    const int py    = tid >> 5;                // 0..7

    const int x0 = tileX * 32;
    const int y0 = tileY * 16;

    float accA[16], accB[16];
#pragma unroll
    for (int i = 0; i < 16; ++i) { accA[i] = 0.f; accB[i] = 0.f; }

    for (int phase = 0; phase < 2; ++phase) {
        const float* inp = phase ? in2 : in1;
        const float* wp  = phase ? w2  : w1;
        const int    Cin = phase ? cin2 : cin1;
        const long   bst = phase ? (long)CH*HW : in1_bstride;
        if (Cin == 0) continue;
        const float* inb = inp + (long)b * bst;

        for (int cin = 0; cin < Cin; ++cin) {
            __syncthreads();   // protect smem from previous iteration's readers
            const float* ic = inb + (long)cin * HW;
            // cooperative halo load: 18x34 = 612 elems
            for (int i = tid; i < 18*34; i += 256) {
                int r = i / 34, c = i - r*34;
                int gy = y0 + r - 1, gx = x0 + c - 1;
                float v = 0.f;
                if ((unsigned)gy < 64u && (unsigned)gx < 64u) v = ic[gy*WW + gx];
                s_in[r][c] = v;
            }
            if (tid < 144) {
                int oo = tid / 9, k = tid - oo*9;
                s_w[oo][k] = wp[((long)(oBase + oo) * Cin + cin) * 9 + k];
            }
            __syncthreads();

            float iA[9], iB[9];
#pragma unroll
            for (int dy = 0; dy < 3; ++dy)
#pragma unroll
                for (int dx = 0; dx < 3; ++dx) {
                    iA[dy*3+dx] = s_in[py + dy][px + dx];
                    iB[dy*3+dx] = s_in[py + 8 + dy][px + dx];
                }
#pragma unroll
            for (int oo = 0; oo < 16; ++oo) {
#pragma unroll
                for (int k = 0; k < 9; ++k) {
                    float w = s_w[oo][k];
                    accA[oo] = fmaf(w, iA[k], accA[oo]);
                    accB[oo] = fmaf(w, iB[k], accB[oo]);
                }
            }
        }
    }

    float* ob = out + (long)b * out_bstride;
#pragma unroll
    for (int oo = 0; oo < 16; ++oo) {
        int o = oBase + oo;
        float bias = b1[o] + (b2 ? b2[o] : 0.f);
        ob[(long)o*HW + (y0 + py    )*WW + (x0 + px)] = accA[oo] + bias;
        ob[(long)o*HW + (y0 + py + 8)*WW + (x0 + px)] = accB[oo] + bias;
    }
}

// ---- fused LSTM pointwise: gates [i,f,g,o] -> update (h, c) in place ----
__global__ void lstm_pointwise(float* __restrict__ hbuf, float* __restrict__ cbuf)
{
    const int n = BB*CH*HW;
    int idx = blockIdx.x*blockDim.x + threadIdx.x;
    if (idx >= n) return;
    int p  = idx & (HW - 1);
    int ch = (idx >> 12) & (CH - 1);
    int b  = idx >> (12 + 7);
    const float* gb = g_gates + (long)b * GG * HW;
    float gi = gb[(ch         )*HW + p];
    float gf = gb[(ch +   CH  )*HW + p];
    float gg = gb[(ch + 2*CH  )*HW + p];
    float go = gb[(ch + 3*CH  )*HW + p];
    float i = 1.f / (1.f + expf(-gi));
    float f = 1.f / (1.f + expf(-gf));
    float g = tanhf(gg);
    float o = 1.f / (1.f + expf(-go));
    float c = f * cbuf[idx] + i * g;
    float h = o * tanhf(c);
    cbuf[idx] = c;
    hbuf[idx] = h;
}

extern "C" void kernel_launch(void* const* d_in, const int* in_sizes, int n_in,
                              void* d_out, int out_size)
{
    const float* target = (const float*)d_in[0];
    const float* h0     = (const float*)d_in[1];
    const float* c0     = (const float*)d_in[2];
    const float* h1     = (const float*)d_in[3];
    const float* c1     = (const float*)d_in[4];
    const float* wi0    = (const float*)d_in[5];
    const float* bi0    = (const float*)d_in[6];
    const float* wh0    = (const float*)d_in[7];
    const float* bh0    = (const float*)d_in[8];
    const float* wi1    = (const float*)d_in[9];
    const float* bi1    = (const float*)d_in[10];
    const float* wh1    = (const float*)d_in[11];
    const float* bh1    = (const float*)d_in[12];
    const float* wtop   = (const float*)d_in[13];
    const float* btop   = (const float*)d_in[14];
    float* out = (float*)d_out;

    float *ph0, *pc0, *ph1, *pc1, *pg;
    cudaGetSymbolAddress((void**)&ph0, g_h0);
    cudaGetSymbolAddress((void**)&pc0, g_c0);
    cudaGetSymbolAddress((void**)&ph1, g_h1);
    cudaGetSymbolAddress((void**)&pc1, g_c1);
    cudaGetSymbolAddress((void**)&pg,  g_gates);

    const long SB = (long)CH*HW;           // state batch stride
    const long TB = (long)TT*CX*HW;        // target/output batch stride
    const long GB = (long)GG*HW;           // gates batch stride

    // init state buffers
    init_states<<<4096, 256>>>(h0, c0, h1, c1);

    // out[:, 0] = conv(h1_initial, wtop) + btop   (reads the pristine input)
    conv3x3_kernel<<<dim3(8, CX/16, BB), 256>>>(
        h1, CH, SB, wtop, btop,
        nullptr, 0, nullptr, nullptr,
        out, TB);

    const int NPW = BB*CH*HW;
    for (int t = 0; t < TT - 1; ++t) {
        // layer 0: gates = conv(x_t, wi0)+bi0 + conv(h0, wh0)+bh0
        conv3x3_kernel<<<dim3(8, GG/16, BB), 256>>>(
            target + (long)t*CX*HW, CX, TB, wi0, bi0,
            ph0, CH, wh0, bh0,
            pg, GB);
        lstm_pointwise<<<(NPW + 255)/256, 256>>>(ph0, pc0);   // h0 <- x1

        // layer 1: gates = conv(x1, wi1)+bi1 + conv(h1, wh1)+bh1
        conv3x3_kernel<<<dim3(8, GG/16, BB), 256>>>(
            ph0, CH, SB, wi1, bi1,
            ph1, CH, wh1, bh1,
            pg, GB);
        lstm_pointwise<<<(NPW + 255)/256, 256>>>(ph1, pc1);   // h1 <- x2

        // out[:, t+1] = conv(x2, wtop) + btop
        conv3x3_kernel<<<dim3(8, CX/16, BB), 256>>>(
            ph1, CH, SB, wtop, btop,
            nullptr, 0, nullptr, nullptr,
            out + (long)(t+1)*CX*HW, TB);
    }
}

// round 5
// speedup vs baseline: 1.3285x; 1.3285x over previous
#include <cuda_runtime.h>

// ConvDecoder: 2-layer ConvLSTM decoder.
// fp32 direct conv using packed fma.rn.f32x2 (FFMA2), 32x32 tile, 4 px/thread.
// B=8, T=10, C=64 in/out, CH=128 hidden, H=W=64, 3x3 'SAME' convs.

#define BB 8
#define TT 10
#define CX 64
#define CH 128
#define HH 64
#define WW 64
#define HW 4096
#define GG (4*CH)   // 512 gate channels

// ---- persistent scratch (device globals; no allocation allowed) ----
__device__ float g_h0[BB*CH*HW];
__device__ float g_c0[BB*CH*HW];
__device__ float g_h1[BB*CH*HW];
__device__ float g_c1[BB*CH*HW];
__device__ float g_gates[BB*GG*HW];

// ---- packed f32x2 helpers (Blackwell FFMA2 path) ----
static __device__ __forceinline__ unsigned long long pack2(float lo, float hi) {
    unsigned long long r;
    asm("mov.b64 %0, {%1, %2};" : "=l"(r) : "f"(lo), "f"(hi));
    return r;
}
static __device__ __forceinline__ void fma2(unsigned long long& d,
                                            unsigned long long a,
                                            unsigned long long b) {
    asm("fma.rn.f32x2 %0, %1, %2, %0;" : "+l"(d) : "l"(a), "l"(b));
}
static __device__ __forceinline__ float2 unpack2(unsigned long long v) {
    float2 r;
    asm("mov.b64 {%0, %1}, %2;" : "=f"(r.x), "=f"(r.y) : "l"(v));
    return r;
}

// ---- copy initial states into mutable buffers ----
__global__ void init_states(const float* __restrict__ h0, const float* __restrict__ c0,
                            const float* __restrict__ h1, const float* __restrict__ c1) {
    int n = BB*CH*HW;
    for (int i = blockIdx.x*blockDim.x + threadIdx.x; i < n; i += gridDim.x*blockDim.x) {
        g_h0[i] = h0[i];
        g_c0[i] = c0[i];
        g_h1[i] = h1[i];
        g_c1[i] = c1[i];
    }
}

// ---- fused 3x3 conv: out = conv(in1,w1)+b1 [+ conv(in2,w2)+b2] ----
// 32x32 output tile, 16 output channels per block, 256 threads.
// Each thread: 4 pixels (rows py, py+8, py+16, py+24) packed as 2 f32x2 pairs.
#define HALO (34*34)
__global__ __launch_bounds__(256, 2)
void conv3x3_kernel(const float* __restrict__ in1, int cin1, long in1_bstride,
                    const float* __restrict__ w1, const float* __restrict__ b1,
                    const float* __restrict__ in2, int cin2,
                    const float* __restrict__ w2, const float* __restrict__ b2,
                    float* __restrict__ out, long out_bstride)
{
    __shared__ float  s_in[HALO];
    __shared__ float2 s_w[16*9];

    const int tid   = threadIdx.x;
    const int tileX = blockIdx.x & 1;          // W/32 = 2
    const int tileY = blockIdx.x >> 1;         // H/32 = 2
    const int oBase = blockIdx.y * 16;
    const int b     = blockIdx.z;
    const int px    = tid & 31;
    const int py    = tid >> 5;                // 0..7

    const int x0 = tileX * 32;
    const int y0 = tileY * 32;

    // ---- precompute halo-load descriptors (hoisted out of the cin loop) ----
    // enc = smem_idx[0:11) | gmem_off[11:23) | valid[23]
    int henc[5];
#pragma unroll
    for (int j = 0; j < 5; ++j) {
        int i = tid + j*256;
        int r = i / 34, c = i - r*34;
        int gy = y0 + r - 1, gx = x0 + c - 1;
        bool ok = (i < HALO) && ((unsigned)gy < 64u) && ((unsigned)gx < 64u);
        int g = ok ? (gy*WW + gx) : 0;
        henc[j] = (i < HALO ? i : 0) | (g << 11) | (ok ? (1 << 23) : 0);
    }
    const bool slot4 = (tid + 4*256) < HALO;

    // weight staging role (threads 0..143)
    const int w_oo = tid / 9;
    const int w_k  = tid - w_oo * 9;
    const bool w_role = tid < 144;

    unsigned long long acc0[16], acc1[16];
    const unsigned long long z = pack2(0.f, 0.f);
#pragma unroll
    for (int i = 0; i < 16; ++i) { acc0[i] = z; acc1[i] = z; }

    for (int phase = 0; phase < 2; ++phase) {
        const float* inp = phase ? in2 : in1;
        const float* wp  = phase ? w2  : w1;
        const int    Cin = phase ? cin2 : cin1;
        const long   bst = phase ? (long)CH*HW : in1_bstride;
        if (Cin == 0) continue;
        const float* ic = inp + (long)b * bst;
        int w_off = w_role ? ((oBase + w_oo) * Cin) * 9 + w_k : 0;

        for (int cin = 0; cin < Cin; ++cin, ic += HW, w_off += 9) {
            __syncthreads();   // protect smem from previous iteration's readers
            // halo load: 34x34
#pragma unroll
            for (int j = 0; j < 4; ++j) {
                int e = henc[j];
                float v = (e >> 23) ? __ldg(ic + ((e >> 11) & 0xFFF)) : 0.f;
                s_in[e & 0x7FF] = v;
            }
            if (slot4) {
                int e = henc[4];
                float v = (e >> 23) ? __ldg(ic + ((e >> 11) & 0xFFF)) : 0.f;
                s_in[e & 0x7FF] = v;
            }
            if (w_role) {
                float w = wp[w_off];
                s_w[tid] = make_float2(w, w);
            }
            __syncthreads();

            // gather 4 pixels x 9 taps into packed registers
            unsigned long long a0[9], a1[9];
#pragma unroll
            for (int dy = 0; dy < 3; ++dy)
#pragma unroll
                for (int dx = 0; dx < 3; ++dx) {
                    const float* base = s_in + (py + dy)*34 + (px + dx);
                    int k = dy*3 + dx;
                    a0[k] = pack2(base[0],      base[8*34]);
                    a1[k] = pack2(base[16*34],  base[24*34]);
                }
#pragma unroll
            for (int oo = 0; oo < 16; ++oo) {
#pragma unroll
                for (int k = 0; k < 9; ++k) {
                    unsigned long long w =
                        *reinterpret_cast<const unsigned long long*>(&s_w[oo*9 + k]);
                    fma2(acc0[oo], a0[k], w);
                    fma2(acc1[oo], a1[k], w);
                }
            }
        }
    }

    float* ob = out + (long)b * out_bstride;
#pragma unroll
    for (int oo = 0; oo < 16; ++oo) {
        int o = oBase + oo;
        float bias = b1[o] + (b2 ? b2[o] : 0.f);
        float2 v0 = unpack2(acc0[oo]);
        float2 v1 = unpack2(acc1[oo]);
        float* p = ob + (long)o*HW + (y0 + py)*WW + (x0 + px);
        p[0]      = v0.x + bias;
        p[8*WW]   = v0.y + bias;
        p[16*WW]  = v1.x + bias;
        p[24*WW]  = v1.y + bias;
    }
}

// ---- fused LSTM pointwise: gates [i,f,g,o] -> update (h, c), float4 ----
static __device__ __forceinline__ float fsig(float x) {
    return __fdividef(1.f, 1.f + __expf(-x));
}
static __device__ __forceinline__ float ftanh(float x) {
    // 2*sigmoid(2x) - 1; saturates correctly at +-1 via expf->inf/0
    return __fdividef(2.f, 1.f + __expf(-2.f*x)) - 1.f;
}

__global__ void lstm_pointwise(float* __restrict__ hbuf, float* __restrict__ cbuf)
{
    const int n4 = BB*CH*HW/4;
    int idx = blockIdx.x*blockDim.x + threadIdx.x;
    if (idx >= n4) return;
    int e  = idx << 2;                 // element index
    int p  = e & (HW - 1);
    int ch = (e >> 12) & (CH - 1);
    int b  = e >> 19;
    const float* gb = g_gates + (long)b * GG * HW;
    float4 gi = *(const float4*)(gb + (ch         )*HW + p);
    float4 gf = *(const float4*)(gb + (ch +   CH  )*HW + p);
    float4 gg = *(const float4*)(gb + (ch + 2*CH  )*HW + p);
    float4 go = *(const float4*)(gb + (ch + 3*CH  )*HW + p);
    float4 c  = *(float4*)(cbuf + e);
    float4 h;

    {
        float i_ = fsig(gi.x), f_ = fsig(gf.x), g_ = ftanh(gg.x), o_ = fsig(go.x);
        c.x = f_*c.x + i_*g_;  h.x = o_*ftanh(c.x);
    }
    {
        float i_ = fsig(gi.y), f_ = fsig(gf.y), g_ = ftanh(gg.y), o_ = fsig(go.y);
        c.y = f_*c.y + i_*g_;  h.y = o_*ftanh(c.y);
    }
    {
        float i_ = fsig(gi.z), f_ = fsig(gf.z), g_ = ftanh(gg.z), o_ = fsig(go.z);
        c.z = f_*c.z + i_*g_;  h.z = o_*ftanh(c.z);
    }
    {
        float i_ = fsig(gi.w), f_ = fsig(gf.w), g_ = ftanh(gg.w), o_ = fsig(go.w);
        c.w = f_*c.w + i_*g_;  h.w = o_*ftanh(c.w);
    }

    *(float4*)(cbuf + e) = c;
    *(float4*)(hbuf + e) = h;
}

extern "C" void kernel_launch(void* const* d_in, const int* in_sizes, int n_in,
                              void* d_out, int out_size)
{
    const float* target = (const float*)d_in[0];
    const float* h0     = (const float*)d_in[1];
    const float* c0     = (const float*)d_in[2];
    const float* h1     = (const float*)d_in[3];
    const float* c1     = (const float*)d_in[4];
    const float* wi0    = (const float*)d_in[5];
    const float* bi0    = (const float*)d_in[6];
    const float* wh0    = (const float*)d_in[7];
    const float* bh0    = (const float*)d_in[8];
    const float* wi1    = (const float*)d_in[9];
    const float* bi1    = (const float*)d_in[10];
    const float* wh1    = (const float*)d_in[11];
    const float* bh1    = (const float*)d_in[12];
    const float* wtop   = (const float*)d_in[13];
    const float* btop   = (const float*)d_in[14];
    float* out = (float*)d_out;

    float *ph0, *pc0, *ph1, *pc1, *pg;
    cudaGetSymbolAddress((void**)&ph0, g_h0);
    cudaGetSymbolAddress((void**)&pc0, g_c0);
    cudaGetSymbolAddress((void**)&ph1, g_h1);
    cudaGetSymbolAddress((void**)&pc1, g_c1);
    cudaGetSymbolAddress((void**)&pg,  g_gates);

    const long SB = (long)CH*HW;           // state batch stride
    const long TB = (long)TT*CX*HW;        // target/output batch stride
    const long GB = (long)GG*HW;           // gates batch stride

    init_states<<<4096, 256>>>(h0, c0, h1, c1);

    // out[:, 0] = conv(h1_initial, wtop) + btop   (reads the pristine input)
    conv3x3_kernel<<<dim3(4, CX/16, BB), 256>>>(
        h1, CH, SB, wtop, btop,
        nullptr, 0, nullptr, nullptr,
        out, TB);

    const int NPW4 = BB*CH*HW/4;
    for (int t = 0; t < TT - 1; ++t) {
        // layer 0: gates = conv(x_t, wi0)+bi0 + conv(h0, wh0)+bh0
        conv3x3_kernel<<<dim3(4, GG/16, BB), 256>>>(
            target + (long)t*CX*HW, CX, TB, wi0, bi0,
            ph0, CH, wh0, bh0,
            pg, GB);
        lstm_pointwise<<<(NPW4 + 255)/256, 256>>>(ph0, pc0);   // h0 <- x1

        // layer 1: gates = conv(x1, wi1)+bi1 + conv(h1, wh1)+bh1
        conv3x3_kernel<<<dim3(4, GG/16, BB), 256>>>(
            ph0, CH, SB, wi1, bi1,
            ph1, CH, wh1, bh1,
            pg, GB);
        lstm_pointwise<<<(NPW4 + 255)/256, 256>>>(ph1, pc1);   // h1 <- x2

        // out[:, t+1] = conv(x2, wtop) + btop
        conv3x3_kernel<<<dim3(4, CX/16, BB), 256>>>(
            ph1, CH, SB, wtop, btop,
            nullptr, 0, nullptr, nullptr,
            out + (long)(t+1)*CX*HW, TB);
    }
}